// round 7
// baseline (speedup 1.0000x reference)
#include <cuda_runtime.h>
#include <math.h>
#include <stdint.h>

#define DK 256
#define DEMB 768
#define CH 32
#define TMAX 1000
#define PMAX 200
#define NCHS_MAX ((TMAX + CH - 1) / CH)   // 32
#define NCHP_MAX ((PMAX + CH - 1) / CH)   // 7

#define S_DECAY 0.95f
#define P_DECAY 0.99f
#define ALPHA   0.1f
#define BETA    1.0f
#define EPSN    1e-12f

// ---------------- device scratch ----------------
__device__ float g_K [TMAX*DK];   // raw K (k_kv output)
__device__ float g_Kn[TMAX*DK];   // normalized K (prep output)
__device__ float g_V [TMAX*DK];   // raw V
__device__ float g_PK[PMAX*DK];   // normalized PK (prep output)
__device__ float g_PV[PMAX*DK];   // raw PV (prep output)
__device__ float g_W[(NCHS_MAX + 2*NCHP_MAX)*CH*DK];
__device__ float g_c[NCHP_MAX*CH];
__device__ float g_res[4*DK];

// ---------------- helpers ----------------
__device__ __forceinline__ unsigned long long pack2(float lo, float hi) {
    unsigned long long r;
    asm("mov.b64 %0, {%1, %2};" : "=l"(r) : "f"(lo), "f"(hi));
    return r;
}
__device__ __forceinline__ unsigned long long fma2(unsigned long long a,
                                                   unsigned long long b,
                                                   unsigned long long c) {
    unsigned long long d;
    asm("fma.rn.f32x2 %0, %1, %2, %3;" : "=l"(d) : "l"(a), "l"(b), "l"(c));
    return d;
}
__device__ __forceinline__ void unpack2(unsigned long long v, float& lo, float& hi) {
    asm("mov.b64 {%0, %1}, %2;" : "=f"(lo), "=f"(hi) : "l"(v));
}
__device__ __forceinline__ uint32_t smem_u32(const void* p) {
    uint32_t a;
    asm("{ .reg .u64 t; cvta.to.shared.u64 t, %1; cvt.u32.u64 %0, t; }" : "=r"(a) : "l"(p));
    return a;
}
__device__ __forceinline__ void cpasync16(uint32_t dst, const void* src) {
    asm volatile("cp.async.cg.shared.global [%0], [%1], 16;" :: "r"(dst), "l"(src));
}
__device__ __forceinline__ void cpasync_commit() {
    asm volatile("cp.async.commit_group;" ::: "memory");
}
template<int N>
__device__ __forceinline__ void cpasync_wait() {
    asm volatile("cp.async.wait_group %0;" :: "n"(N) : "memory");
}

// ---------------- kernel 1: K/V projection — output-stationary tiling ----------------
// Block = 56 emb rows × 64 output cols (of combined 512 = Wk|Wv). Grid 18×8 = 144
// blocks = single wave. emb tile transposed & resident in smem; weight tile streamed
// in 12 double-buffered cp.async stages. Weight traffic 27MB (was 187MB).
#define RT_ROWS 56
#define CT_COLS 64
#define WE 64                      // e-rows per weight stage
#define KV_NST (DEMB / WE)         // 12
#define EST_STRIDE 58              // even (f32x2-aligned pairs), gcd(58,32)=2
#define WS_FLOATS (WE * CT_COLS)   // 4096 floats = 16KB per buffer
#define KV_EST_OFF (2 * WS_FLOATS) // 8192 floats
#define KV_DYN_BYTES ((KV_EST_OFF + DEMB*EST_STRIDE) * 4)   // 210,944 B

__global__ void __launch_bounds__(256, 1) k_kv(const float* __restrict__ emb,
                     const float* __restrict__ Wk, const float* __restrict__ bk,
                     const float* __restrict__ Wv, const float* __restrict__ bv,
                     int T)
{
    extern __shared__ __align__(16) float dynkv[];
    float* ws  = dynkv;                  // 2 × 4096 floats
    float* est = dynkv + KV_EST_OFF;     // est[e*58 + r], r in [0,56)

    const int tid = threadIdx.x;
    const int rt  = blockIdx.x >> 3;
    const int ct  = blockIdx.x & 7;
    const int r0  = rt * RT_ROWS;
    const bool isK = (ct < 4);
    const float* Wsel = isK ? Wk : Wv;
    const int c0 = (ct & 3) * CT_COLS;   // col offset within 256
    const int c  = tid & 63;             // col within tile
    const int g  = tid >> 6;             // row group 0..3 (14 rows each)
    const uint32_t wsb = smem_u32(ws);

    // load emb tile transposed: est[e][r]
    for (int i4 = tid; i4 < RT_ROWS*(DEMB/4); i4 += 256) {
        int r  = i4 / (DEMB/4);
        int e4 = (i4 - r*(DEMB/4)) * 4;
        float4 v = make_float4(0.f, 0.f, 0.f, 0.f);
        if (r0 + r < T) v = *(const float4*)&emb[(size_t)(r0 + r)*DEMB + e4];
        est[(e4    )*EST_STRIDE + r] = v.x;
        est[(e4 + 1)*EST_STRIDE + r] = v.y;
        est[(e4 + 2)*EST_STRIDE + r] = v.z;
        est[(e4 + 3)*EST_STRIDE + r] = v.w;
    }

    auto issue = [&](int s) {            // stage s -> buffer s&1 (16KB, 1024 chunks)
        int buf = s & 1;
        #pragma unroll
        for (int t = 0; t < 4; t++) {
            int idx = tid + 256*t;
            int el = idx >> 4, ch = idx & 15;
            cpasync16(wsb + (uint32_t)(buf*WS_FLOATS + el*CT_COLS + ch*4) * 4u,
                      Wsel + (size_t)(s*WE + el)*DK + c0 + ch*4);
        }
        cpasync_commit();
    };
    issue(0); issue(1);

    unsigned long long acc[7];
    #pragma unroll
    for (int p = 0; p < 7; p++) acc[p] = pack2(0.f, 0.f);

    __syncthreads();   // est visible (stage-0 weights gated by wait below)

    for (int s = 0; s < KV_NST; s++) {
        cpasync_wait<1>();               // stage s landed (own chunks)
        __syncthreads();                 // all threads' chunks visible
        const float* w  = ws + (s & 1) * WS_FLOATS;
        const float* eb = est + (size_t)s * WE * EST_STRIDE + g*14;

        #pragma unroll 8
        for (int el = 0; el < WE; el++) {
            float wv = w[el*CT_COLS + c];
            unsigned long long w2 = pack2(wv, wv);
            const float* ep = eb + el*EST_STRIDE;
            #pragma unroll
            for (int p = 0; p < 7; p++) {
                unsigned long long pr = *(const unsigned long long*)(ep + 2*p);
                acc[p] = fma2(pr, w2, acc[p]);
            }
        }
        __syncthreads();                 // buffer s&1 free for reuse
        if (s + 2 < KV_NST) issue(s + 2);
    }

    const float* bsel = isK ? bk : bv;
    float* osel = isK ? g_K : g_V;
    float bb = bsel[c0 + c];
    #pragma unroll
    for (int p = 0; p < 7; p++) {
        float v0, v1;
        unpack2(acc[p], v0, v1);
        int r = r0 + g*14 + 2*p;
        if (r < T)     osel[(size_t)r*DK     + c0 + c] = v0 + bb;
        if (r + 1 < T) osel[(size_t)(r+1)*DK + c0 + c] = v1 + bb;
    }
}

// ---------------- kernel 2: fused means + norm + Gram + inverse + W + constants --------
__global__ void __launch_bounds__(256) k_prep(int T, int P, int nchS, int nchP)
{
    extern __shared__ __align__(16) float dyn[];
    float* ks = dyn;            // 32*260
    float* vs = dyn + 8320;     // 32*260 (para only)
    __shared__ float Gs[CH*33];
    __shared__ __align__(16) float Ts[CH*36];
    __shared__ float Pm[CH];
    __shared__ float fs[CH], lfs[CH];

    const int cid = blockIdx.x, tid = threadIdx.x;
    const int wid = tid >> 5, lane = tid & 31;

    int type, chunk, steps;
    if (cid < nchS)              { type = 0; chunk = cid;               steps = T; }
    else if (cid < nchS + nchP)  { type = 1; chunk = cid - nchS;        steps = P; }
    else                         { type = 2; chunk = cid - nchS - nchP; steps = P; }
    const int lo  = chunk * CH;
    const int len = min(CH, steps - lo);
    const bool bwd = (type <= 1);
    const bool isPara = (type >= 1);

    if (!isPara) {
        #pragma unroll
        for (int u = 0; u < 8; u++) {
            int id = tid + 256*u;
            int a = id >> 6, c4 = (id & 63) * 4;
            float4 v = make_float4(0.f, 0.f, 0.f, 0.f);
            if (a < len) v = *(const float4*)&g_K[(lo + a)*DK + c4];
            *(float4*)&ks[a*260 + c4] = v;
        }
    } else {
        #pragma unroll
        for (int g = 0; g < 8; g++) {
            int r  = (tid >> 6) + 4*g;
            int c4 = (tid & 63) * 4;
            float4 ak = make_float4(0.f,0.f,0.f,0.f);
            float4 av = make_float4(0.f,0.f,0.f,0.f);
            if (r < len) {
                #pragma unroll
                for (int i = 0; i < 5; i++) {
                    float4 kk = *(const float4*)&g_K[((lo + r)*5 + i)*DK + c4];
                    float4 vv = *(const float4*)&g_V[((lo + r)*5 + i)*DK + c4];
                    ak.x += kk.x; ak.y += kk.y; ak.z += kk.z; ak.w += kk.w;
                    av.x += vv.x; av.y += vv.y; av.z += vv.z; av.w += vv.w;
                }
                ak.x *= 0.2f; ak.y *= 0.2f; ak.z *= 0.2f; ak.w *= 0.2f;
                av.x *= 0.2f; av.y *= 0.2f; av.z *= 0.2f; av.w *= 0.2f;
                if (type == 1) *(float4*)&g_PV[(lo + r)*DK + c4] = av;
            }
            *(float4*)&ks[r*260 + c4] = ak;
            *(float4*)&vs[r*260 + c4] = av;
        }
    }
    __syncthreads();

    if (type == 2) {
        #pragma unroll
        for (int rr = 0; rr < 4; rr++) {
            int r = wid*4 + rr;
            float s = 0.f;
            #pragma unroll
            for (int m = 0; m < 8; m++) s += vs[r*260 + lane + 32*m];
            #pragma unroll
            for (int o = 16; o; o >>= 1) s += __shfl_xor_sync(0xffffffffu, s, o);
            if (lane == 0) Pm[r] = s * (1.f/256.f);
        }
    }

    {
        float* gout = isPara ? g_PK : g_Kn;
        const bool wr = (type != 2);
        #pragma unroll
        for (int rr = 0; rr < 4; rr++) {
            int r = wid*4 + rr;
            float v[8]; float s = 0.f;
            #pragma unroll
            for (int m = 0; m < 8; m++) { v[m] = ks[r*260 + lane + 32*m]; s += v[m]*v[m]; }
            #pragma unroll
            for (int o = 16; o; o >>= 1) s += __shfl_xor_sync(0xffffffffu, s, o);
            float rinv = 1.f / fmaxf(sqrtf(s), EPSN);
            #pragma unroll
            for (int m = 0; m < 8; m++) {
                float nv = v[m] * rinv;
                ks[r*260 + lane + 32*m] = nv;
                if (wr && r < len) gout[(lo + r)*DK + lane + 32*m] = nv;
            }
        }
    }
    __syncthreads();

    {
        float acc[4] = {0.f, 0.f, 0.f, 0.f};
        #pragma unroll 8
        for (int i4 = 0; i4 < 64; i4++) {
            float4 own = *(const float4*)&ks[lane*260 + i4*4];
            #pragma unroll
            for (int s = 0; s < 4; s++) {
                float4 b = *(const float4*)&ks[(wid + 8*s)*260 + i4*4];
                acc[s] += own.x*b.x + own.y*b.y + own.z*b.z + own.w*b.w;
            }
        }
        #pragma unroll
        for (int s = 0; s < 4; s++) Gs[(wid + 8*s)*33 + lane] = acc[s];
    }
    __syncthreads();

    #pragma unroll
    for (int cc = 0; cc < 4; cc++) {
        int k = wid*4 + cc;
        float v = (lane == k) ? 1.f : 0.f;
        for (int i = 0; i < len; i++) {
            float vi = __shfl_sync(0xffffffffu, v, i);
            if (lane > i && lane < len) {
                float g = bwd ? Gs[(len-1-lane)*33 + (len-1-i)]
                              : Gs[lane*33 + i];
                v -= ALPHA * g * vi;
            }
        }
        Ts[lane*36 + k] = v;
    }
    __syncthreads();

    if (type == 2 && wid == 0) {
        float f = 0.f;
        if (lane < len) {
            float dp = 1.f;
            for (int i = 0; i <= lane; i++) dp *= (1.f / P_DECAY);
            f = BETA * dp * Pm[lane];
        }
        fs[lane] = f;
        __syncwarp();
        float lf = 0.f;
        if (lane < len)
            for (int i = 0; i < lane; i++) lf += Gs[lane*33 + i] * fs[i];
        lfs[lane] = lf;
        __syncwarp();
        float e = 0.f;
        #pragma unroll 8
        for (int k2 = 0; k2 < CH; k2++) e += Ts[lane*36 + k2] * lfs[k2];
        g_c[chunk*CH + lane] = -ALPHA * e + f;
    }

    float ksv[CH];
    #pragma unroll
    for (int m = 0; m < CH; m++) {
        int rl = bwd ? (len - 1 - m) : m;
        ksv[m] = (m < len) ? ks[rl*260 + tid] : 0.f;
    }
    float* Wout = g_W + (size_t)cid * CH * DK;
    #pragma unroll
    for (int j = 0; j < CH; j++) {
        float acc2 = 0.f;
        #pragma unroll
        for (int m4 = 0; m4 < 8; m4++) {
            float4 t = *(const float4*)&Ts[j*36 + m4*4];
            acc2 += t.x*ksv[m4*4] + t.y*ksv[m4*4+1] + t.z*ksv[m4*4+2] + t.w*ksv[m4*4+3];
        }
        Wout[j*DK + tid] = acc2;
    }
}

// ---------------- kernel 3: chunked probe scans (4 concurrent blocks) ----------------
__global__ void __launch_bounds__(256) k_scan(const float* __restrict__ q,
                                              int T, int P, int nchS, int nchP)
{
    __shared__ float a_s[DK];
    __shared__ float sigk_s[CH], sigv_s[CH];
    __shared__ float dpow[CH+1];
    __shared__ float red[8];
    __shared__ float s_inv;

    const int bid = blockIdx.x, tid = threadIdx.x;
    const int wid = tid >> 5, lane = tid & 31;
    const bool fwd  = (bid == 3);
    const bool sent = (bid == 0);
    const float decay = sent ? S_DECAY : P_DECAY;
    const int nch   = sent ? nchS : nchP;
    const int steps = sent ? T : P;
    const float* Kd = sent ? g_Kn : g_PK;
    const float* Vd = sent ? g_V  : g_PV;
    const int slot0 = sent ? 0 : (fwd ? (nchS + nchP) : nchS);

    if (tid == 0) {
        dpow[0] = 1.f;
        for (int i = 0; i < CH; i++) dpow[i+1] = dpow[i] * decay;
    }

    float a;
    if (bid <= 1) {
        float qv = q[tid];
        float x = qv * qv;
        #pragma unroll
        for (int o = 16; o; o >>= 1) x += __shfl_xor_sync(0xffffffffu, x, o);
        if (lane == 0) red[wid] = x;
        __syncthreads();
        if (tid == 0) {
            float s = 0.f;
            #pragma unroll
            for (int w = 0; w < 8; w++) s += red[w];
            s_inv = 1.f / fmaxf(sqrtf(s), EPSN);
        }
        __syncthreads();
        a = qv * s_inv;
    } else {
        a = (bid == 2) ? (1.f/256.f) : 0.f;
    }
    a_s[tid] = a;

    const int j0 = wid * 4;
    float wreg[4][8];
    float creg[4] = {0.f, 0.f, 0.f, 0.f};

    {
        int chunk = fwd ? 0 : (nch - 1);
        const float* Wp = g_W + (size_t)(slot0 + chunk) * CH * DK;
        #pragma unroll
        for (int r = 0; r < 4; r++)
            #pragma unroll
            for (int m = 0; m < 8; m++)
                wreg[r][m] = Wp[(j0 + r)*DK + lane + 32*m];
        if (fwd) {
            #pragma unroll
            for (int r = 0; r < 4; r++) creg[r] = g_c[chunk*CH + j0 + r];
        }
    }

    float outreg = 0.f;

    for (int c = 0; c < nch; c++) {
        const int chunk = fwd ? c : (nch - 1 - c);
        const int lo  = chunk * CH;
        const int len = min(CH, steps - lo);
        const int hi  = lo + len - 1;
        __syncthreads();

        float kreg[CH], vreg[CH];
        #pragma unroll
        for (int j = 0; j < CH; j++) {
            int row = fwd ? (lo + j) : (hi - j);
            row = max(0, min(row, steps - 1));
            kreg[j] = Kd[row*DK + tid];
            vreg[j] = fwd ? 0.f : Vd[row*DK + tid];
        }

        float av[8];
        #pragma unroll
        for (int m = 0; m < 8; m++) av[m] = a_s[lane + 32*m];
        float s[4];
        #pragma unroll
        for (int r = 0; r < 4; r++) {
            float t = 0.f;
            #pragma unroll
            for (int m = 0; m < 8; m++) t += wreg[r][m] * av[m];
            s[r] = t;
        }
        #pragma unroll
        for (int o = 16; o; o >>= 1)
            #pragma unroll
            for (int r = 0; r < 4; r++)
                s[r] += __shfl_xor_sync(0xffffffffu, s[r], o);
        if (lane == 0) {
            #pragma unroll
            for (int r = 0; r < 4; r++) {
                int j = j0 + r;
                float sk = 0.f, sv = 0.f;
                if (j < len) {
                    if (fwd) { sk = -ALPHA * s[r] + creg[r]; }
                    else     { sk = -ALPHA * s[r]; sv = BETA * dpow[j] * s[r]; }
                }
                sigk_s[j] = sk;
                sigv_s[j] = sv;
            }
        }

        if (c + 1 < nch) {
            int nchunk = fwd ? (c + 1) : (nch - 2 - c);
            const float* Wp = g_W + (size_t)(slot0 + nchunk) * CH * DK;
            #pragma unroll
            for (int r = 0; r < 4; r++)
                #pragma unroll
                for (int m = 0; m < 8; m++)
                    wreg[r][m] = Wp[(j0 + r)*DK + lane + 32*m];
            if (fwd) {
                #pragma unroll
                for (int r = 0; r < 4; r++) creg[r] = g_c[nchunk*CH + j0 + r];
            }
        }
        __syncthreads();

        float wsum = 0.f, osum = 0.f;
        #pragma unroll
        for (int j = 0; j < CH; j++) {
            wsum += sigk_s[j] * kreg[j];
            osum += sigv_s[j] * vreg[j];
        }
        outreg += osum;
        a = dpow[len] * (a + wsum);
        a_s[tid] = a;
    }

    if (bid < 3) g_res[bid*DK + tid] = outreg;
    else         g_res[3*DK + tid]   = a;
}

// ---------------- kernel 4: combine ----------------
__device__ __forceinline__ float bred256(float x, float* red)
{
    const int tid = threadIdx.x;
    #pragma unroll
    for (int o = 16; o; o >>= 1) x += __shfl_xor_sync(0xffffffffu, x, o);
    __syncthreads();
    if ((tid & 31) == 0) red[tid >> 5] = x;
    __syncthreads();
    float s = 0.f;
    #pragma unroll
    for (int w = 0; w < 8; w++) s += red[w];
    return s;
}

__global__ void k_final(const float* __restrict__ q, float* __restrict__ out)
{
    __shared__ float red[8];
    const int tid = threadIdx.x;
    float qv  = q[tid];
    float dkv = g_res[3*256 + tid];
    float ssq = bred256(qv*qv, red);
    float ssd = bred256(dkv*dkv, red);
    float dot = bred256(qv*dkv, red);
    float coef = dot / (fmaxf(sqrtf(ssq), EPSN) * fmaxf(sqrtf(ssd), EPSN));
    out[tid] = 0.2f*g_res[tid] + 0.3f*g_res[256 + tid]
             + 0.5f * (BETA * coef) * g_res[512 + tid];
}

// ---------------- launcher ----------------
extern "C" void kernel_launch(void* const* d_in, const int* in_sizes, int n_in,
                              void* d_out, int out_size)
{
    const float* emb = (const float*)d_in[0];
    const float* q   = (const float*)d_in[1];
    const float* Wk  = (const float*)d_in[2];
    const float* bk  = (const float*)d_in[3];
    const float* Wv  = (const float*)d_in[4];
    const float* bv  = (const float*)d_in[5];
    // d_in[6..8] = zero initial memories (collapsed analytically)

    int T = in_sizes[0] / DEMB;     // 1000
    int P = T / 5;                  // 200
    int nchS = (T + CH - 1) / CH;   // 32
    int nchP = (P + CH - 1) / CH;   // 7
    int nRT  = (T + RT_ROWS - 1) / RT_ROWS;   // 18

    cudaFuncSetAttribute(k_kv, cudaFuncAttributeMaxDynamicSharedMemorySize, KV_DYN_BYTES);
    cudaFuncSetAttribute(k_prep, cudaFuncAttributeMaxDynamicSharedMemorySize, 16640*4);

    k_kv  <<<nRT*8, 256, KV_DYN_BYTES>>>(emb, Wk, bk, Wv, bv, T);
    k_prep<<<nchS + 2*nchP, 256, 16640*4>>>(T, P, nchS, nchP);
    k_scan<<<4, 256>>>(q, T, P, nchS, nchP);
    k_final<<<1, 256>>>(q, (float*)d_out);
}

// round 8
// speedup vs baseline: 1.1190x; 1.1190x over previous
#include <cuda_runtime.h>
#include <math.h>
#include <stdint.h>

#define DK 256
#define DEMB 768
#define CH 32
#define TMAX 1000
#define PMAX 200
#define NCHS_MAX ((TMAX + CH - 1) / CH)   // 32
#define NCHP_MAX ((PMAX + CH - 1) / CH)   // 7

#define S_DECAY 0.95f
#define P_DECAY 0.99f
#define ALPHA   0.1f
#define BETA    1.0f
#define EPSN    1e-12f

// ---------------- device scratch ----------------
__device__ float g_K [TMAX*DK];
__device__ float g_Kn[TMAX*DK];
__device__ float g_V [TMAX*DK];
__device__ float g_PK[PMAX*DK];
__device__ float g_PV[PMAX*DK];
__device__ float g_W[(NCHS_MAX + 2*NCHP_MAX)*CH*DK];
__device__ float g_c[NCHP_MAX*CH];
__device__ float g_res[4*DK];
__device__ int   g_bar1 = 0, g_bar2 = 0, g_done = 0;

// ---------------- helpers ----------------
__device__ __forceinline__ unsigned long long pack2(float lo, float hi) {
    unsigned long long r;
    asm("mov.b64 %0, {%1, %2};" : "=l"(r) : "f"(lo), "f"(hi));
    return r;
}
__device__ __forceinline__ unsigned long long fma2(unsigned long long a,
                                                   unsigned long long b,
                                                   unsigned long long c) {
    unsigned long long d;
    asm("fma.rn.f32x2 %0, %1, %2, %3;" : "=l"(d) : "l"(a), "l"(b), "l"(c));
    return d;
}
__device__ __forceinline__ void unpack2(unsigned long long v, float& lo, float& hi) {
    asm("mov.b64 {%0, %1}, %2;" : "=f"(lo), "=f"(hi) : "l"(v));
}
__device__ __forceinline__ uint32_t smem_u32(const void* p) {
    uint32_t a;
    asm("{ .reg .u64 t; cvta.to.shared.u64 t, %1; cvt.u32.u64 %0, t; }" : "=r"(a) : "l"(p));
    return a;
}
__device__ __forceinline__ void mbar_init(uint32_t a, uint32_t n) {
    asm volatile("mbarrier.init.shared.b64 [%0], %1;" :: "r"(a), "r"(n) : "memory");
}
__device__ __forceinline__ void mbar_expect(uint32_t a, uint32_t bytes) {
    asm volatile("mbarrier.arrive.expect_tx.shared.b64 _, [%0], %1;" :: "r"(a), "r"(bytes) : "memory");
}
__device__ __forceinline__ void bulk_g2s(uint32_t dst, const void* src, uint32_t bytes, uint32_t mbar) {
    asm volatile("cp.async.bulk.shared::cluster.global.mbarrier::complete_tx::bytes [%0], [%1], %2, [%3];"
                 :: "r"(dst), "l"(src), "r"(bytes), "r"(mbar) : "memory");
}
__device__ __forceinline__ void mbar_wait(uint32_t a, uint32_t parity) {
    asm volatile(
        "{\n\t.reg .pred P;\n"
        "W_%=:\n\t"
        "mbarrier.try_wait.parity.acquire.cta.shared::cta.b64 P, [%0], %1, 0x989680;\n\t"
        "@P bra.uni D_%=;\n\t"
        "bra.uni W_%=;\n"
        "D_%=:\n\t}"
        :: "r"(a), "r"(parity) : "memory");
}

// ---------------- phase 1: K/V projection (R6 k_kv, verbatim math) ----------------
#define ETILE 32
#define NSTAGE (DEMB / ETILE)     // 24
#define NBUF 3
#define WBUF_FLOATS (ETILE*DK*2)  // 16384 floats
#define EST_OFF (NBUF*WBUF_FLOATS)        // 49152
#define DYN_BYTES ((EST_OFF + DEMB*8) * 4)   // 221184 B

__device__ __forceinline__ void kv_phase(float* dynkv, unsigned long long* mb,
                     const float* __restrict__ emb,
                     const float* __restrict__ Wk, const float* __restrict__ bk,
                     const float* __restrict__ Wv, const float* __restrict__ bv,
                     int T)
{
    float* wbuf = dynkv;
    float* est  = dynkv + EST_OFF;

    const int tid = threadIdx.x;
    const int r0  = blockIdx.x * 8;
    const int rows = min(8, T - r0);
    const uint32_t wbufb = smem_u32(wbuf);
    const int s0 = blockIdx.x % NSTAGE;

    for (int idx = tid; idx < 8*DEMB; idx += 256) {
        int e = idx >> 3, r = idx & 7;
        est[e*8 + r] = (r < rows) ? emb[(r0 + r)*DEMB + e] : 0.f;
    }
    if (tid == 0) {
        #pragma unroll
        for (int i = 0; i < NBUF; i++) mbar_init(smem_u32(&mb[i]), 1);
    }
    __syncthreads();

    auto issue = [&](int i) {
        int s = s0 + i; if (s >= NSTAGE) s -= NSTAGE;
        int buf = i % NBUF;
        uint32_t mba = smem_u32(&mb[buf]);
        uint32_t dst = wbufb + (uint32_t)buf * (WBUF_FLOATS*4u);
        mbar_expect(mba, WBUF_FLOATS*4u);
        bulk_g2s(dst,               Wk + s*ETILE*DK, ETILE*DK*4u, mba);
        bulk_g2s(dst + ETILE*DK*4u, Wv + s*ETILE*DK, ETILE*DK*4u, mba);
    };
    if (tid == 0) { issue(0); issue(1); issue(2); }

    unsigned long long aK[4], aV[4];
    #pragma unroll
    for (int p = 0; p < 4; p++) { aK[p] = pack2(0.f, 0.f); aV[p] = pack2(0.f, 0.f); }

    for (int i = 0; i < NSTAGE; i++) {
        int s = s0 + i; if (s >= NSTAGE) s -= NSTAGE;
        mbar_wait(smem_u32(&mb[i % NBUF]), (i / NBUF) & 1);
        const float* Wks = wbuf + (i % NBUF) * WBUF_FLOATS;
        const float* Wvs = Wks + ETILE*DK;
        const int e0 = s * ETILE;

        #pragma unroll 16
        for (int ee = 0; ee < ETILE; ee++) {
            float wk = Wks[ee*DK + tid];
            float wv = Wvs[ee*DK + tid];
            unsigned long long wk2 = pack2(wk, wk);
            unsigned long long wv2 = pack2(wv, wv);
            const float* ep = &est[(e0 + ee)*8];
            ulonglong2 p01 = *(const ulonglong2*)ep;
            ulonglong2 p23 = *(const ulonglong2*)(ep + 4);
            aK[0] = fma2(p01.x, wk2, aK[0]);  aV[0] = fma2(p01.x, wv2, aV[0]);
            aK[1] = fma2(p01.y, wk2, aK[1]);  aV[1] = fma2(p01.y, wv2, aV[1]);
            aK[2] = fma2(p23.x, wk2, aK[2]);  aV[2] = fma2(p23.x, wv2, aV[2]);
            aK[3] = fma2(p23.y, wk2, aK[3]);  aV[3] = fma2(p23.y, wv2, aV[3]);
        }
        __syncthreads();
        if (tid == 0 && i + NBUF < NSTAGE) issue(i + NBUF);
    }

    float bkv = bk[tid], bvv = bv[tid];
    #pragma unroll
    for (int p = 0; p < 4; p++) {
        float k0,k1,v0,v1;
        unpack2(aK[p], k0, k1);
        unpack2(aV[p], v0, v1);
        int r = 2*p;
        if (r < rows)     { g_K[(r0+r  )*DK + tid] = k0 + bkv; g_V[(r0+r  )*DK + tid] = v0 + bvv; }
        if (r + 1 < rows) { g_K[(r0+r+1)*DK + tid] = k1 + bkv; g_V[(r0+r+1)*DK + tid] = v1 + bvv; }
    }
}

// ---------------- phase 2: prep (R6 k_prep, smem moved into dyn arena) ----------------
__device__ __forceinline__ void prep_phase(float* dyn, int cid,
                                           int T, int P, int nchS, int nchP)
{
    float* ks  = dyn;             // 32*260 = 8320
    float* vs  = dyn + 8320;      // 32*260
    float* Gs  = dyn + 16640;     // 32*33 = 1056
    float* Ts  = dyn + 17696;     // 32*36 = 1152 (16B-aligned rows)
    float* Pm  = dyn + 18848;     // 32
    float* fs  = dyn + 18880;     // 32
    float* lfs = dyn + 18912;     // 32

    const int tid = threadIdx.x;
    const int wid = tid >> 5, lane = tid & 31;

    int type, chunk, steps;
    if (cid < nchS)              { type = 0; chunk = cid;               steps = T; }
    else if (cid < nchS + nchP)  { type = 1; chunk = cid - nchS;        steps = P; }
    else                         { type = 2; chunk = cid - nchS - nchP; steps = P; }
    const int lo  = chunk * CH;
    const int len = min(CH, steps - lo);
    const bool bwd = (type <= 1);
    const bool isPara = (type >= 1);

    if (!isPara) {
        #pragma unroll
        for (int u = 0; u < 8; u++) {
            int id = tid + 256*u;
            int a = id >> 6, c4 = (id & 63) * 4;
            float4 v = make_float4(0.f, 0.f, 0.f, 0.f);
            if (a < len) v = *(const float4*)&g_K[(lo + a)*DK + c4];
            *(float4*)&ks[a*260 + c4] = v;
        }
    } else {
        #pragma unroll
        for (int g = 0; g < 8; g++) {
            int r  = (tid >> 6) + 4*g;
            int c4 = (tid & 63) * 4;
            float4 ak = make_float4(0.f,0.f,0.f,0.f);
            float4 av = make_float4(0.f,0.f,0.f,0.f);
            if (r < len) {
                #pragma unroll
                for (int i = 0; i < 5; i++) {
                    float4 kk = *(const float4*)&g_K[((lo + r)*5 + i)*DK + c4];
                    float4 vv = *(const float4*)&g_V[((lo + r)*5 + i)*DK + c4];
                    ak.x += kk.x; ak.y += kk.y; ak.z += kk.z; ak.w += kk.w;
                    av.x += vv.x; av.y += vv.y; av.z += vv.z; av.w += vv.w;
                }
                ak.x *= 0.2f; ak.y *= 0.2f; ak.z *= 0.2f; ak.w *= 0.2f;
                av.x *= 0.2f; av.y *= 0.2f; av.z *= 0.2f; av.w *= 0.2f;
                if (type == 1) *(float4*)&g_PV[(lo + r)*DK + c4] = av;
            }
            *(float4*)&ks[r*260 + c4] = ak;
            *(float4*)&vs[r*260 + c4] = av;
        }
    }
    __syncthreads();

    if (type == 2) {
        #pragma unroll
        for (int rr = 0; rr < 4; rr++) {
            int r = wid*4 + rr;
            float s = 0.f;
            #pragma unroll
            for (int m = 0; m < 8; m++) s += vs[r*260 + lane + 32*m];
            #pragma unroll
            for (int o = 16; o; o >>= 1) s += __shfl_xor_sync(0xffffffffu, s, o);
            if (lane == 0) Pm[r] = s * (1.f/256.f);
        }
    }

    {
        float* gout = isPara ? g_PK : g_Kn;
        const bool wr = (type != 2);
        #pragma unroll
        for (int rr = 0; rr < 4; rr++) {
            int r = wid*4 + rr;
            float v[8]; float s = 0.f;
            #pragma unroll
            for (int m = 0; m < 8; m++) { v[m] = ks[r*260 + lane + 32*m]; s += v[m]*v[m]; }
            #pragma unroll
            for (int o = 16; o; o >>= 1) s += __shfl_xor_sync(0xffffffffu, s, o);
            float rinv = 1.f / fmaxf(sqrtf(s), EPSN);
            #pragma unroll
            for (int m = 0; m < 8; m++) {
                float nv = v[m] * rinv;
                ks[r*260 + lane + 32*m] = nv;
                if (wr && r < len) gout[(lo + r)*DK + lane + 32*m] = nv;
            }
        }
    }
    __syncthreads();

    {
        float acc[4] = {0.f, 0.f, 0.f, 0.f};
        #pragma unroll 8
        for (int i4 = 0; i4 < 64; i4++) {
            float4 own = *(const float4*)&ks[lane*260 + i4*4];
            #pragma unroll
            for (int s = 0; s < 4; s++) {
                float4 b = *(const float4*)&ks[(wid + 8*s)*260 + i4*4];
                acc[s] += own.x*b.x + own.y*b.y + own.z*b.z + own.w*b.w;
            }
        }
        #pragma unroll
        for (int s = 0; s < 4; s++) Gs[(wid + 8*s)*33 + lane] = acc[s];
    }
    __syncthreads();

    #pragma unroll
    for (int cc = 0; cc < 4; cc++) {
        int k = wid*4 + cc;
        float v = (lane == k) ? 1.f : 0.f;
        for (int i = 0; i < len; i++) {
            float vi = __shfl_sync(0xffffffffu, v, i);
            if (lane > i && lane < len) {
                float g = bwd ? Gs[(len-1-lane)*33 + (len-1-i)]
                              : Gs[lane*33 + i];
                v -= ALPHA * g * vi;
            }
        }
        Ts[lane*36 + k] = v;
    }
    __syncthreads();

    if (type == 2 && wid == 0) {
        float f = 0.f;
        if (lane < len) {
            float dp = 1.f;
            for (int i = 0; i <= lane; i++) dp *= (1.f / P_DECAY);
            f = BETA * dp * Pm[lane];
        }
        fs[lane] = f;
        __syncwarp();
        float lf = 0.f;
        if (lane < len)
            for (int i = 0; i < lane; i++) lf += Gs[lane*33 + i] * fs[i];
        lfs[lane] = lf;
        __syncwarp();
        float e = 0.f;
        #pragma unroll 8
        for (int k2 = 0; k2 < CH; k2++) e += Ts[lane*36 + k2] * lfs[k2];
        g_c[chunk*CH + lane] = -ALPHA * e + f;
    }

    float ksv[CH];
    #pragma unroll
    for (int m = 0; m < CH; m++) {
        int rl = bwd ? (len - 1 - m) : m;
        ksv[m] = (m < len) ? ks[rl*260 + tid] : 0.f;
    }
    float* Wout = g_W + (size_t)cid * CH * DK;
    #pragma unroll
    for (int j = 0; j < CH; j++) {
        float acc2 = 0.f;
        #pragma unroll
        for (int m4 = 0; m4 < 8; m4++) {
            float4 t = *(const float4*)&Ts[j*36 + m4*4];
            acc2 += t.x*ksv[m4*4] + t.y*ksv[m4*4+1] + t.z*ksv[m4*4+2] + t.w*ksv[m4*4+3];
        }
        Wout[j*DK + tid] = acc2;
    }
}

// ---------------- phase 3: scan (R6 k_scan) + final fused into block 0 ----------------
__device__ __forceinline__ float bred256(float x, float* red)
{
    const int tid = threadIdx.x;
    #pragma unroll
    for (int o = 16; o; o >>= 1) x += __shfl_xor_sync(0xffffffffu, x, o);
    __syncthreads();
    if ((tid & 31) == 0) red[tid >> 5] = x;
    __syncthreads();
    float s = 0.f;
    #pragma unroll
    for (int w = 0; w < 8; w++) s += red[w];
    return s;
}

__device__ __forceinline__ void scan_phase(float* dyn, int bid,
                                           const float* __restrict__ q,
                                           float* __restrict__ out,
                                           int T, int P, int nchS, int nchP)
{
    float* a_s    = dyn;            // 256
    float* sigk_s = dyn + 256;      // 32
    float* sigv_s = dyn + 288;      // 32
    float* dpow   = dyn + 320;      // 33
    float* red    = dyn + 356;      // 8
    float* s_invp = dyn + 364;      // 1

    const int tid = threadIdx.x;
    const int wid = tid >> 5, lane = tid & 31;
    const bool fwd  = (bid == 3);
    const bool sent = (bid == 0);
    const float decay = sent ? S_DECAY : P_DECAY;
    const int nch   = sent ? nchS : nchP;
    const int steps = sent ? T : P;
    const float* Kd = sent ? g_Kn : g_PK;
    const float* Vd = sent ? g_V  : g_PV;
    const int slot0 = sent ? 0 : (fwd ? (nchS + nchP) : nchS);

    if (tid == 0) {
        dpow[0] = 1.f;
        for (int i = 0; i < CH; i++) dpow[i+1] = dpow[i] * decay;
    }
    __syncthreads();

    float qv = q[tid];     // loaded for all blocks (block 0 reuses in final)
    float a;
    {
        float x = qv * qv;
        #pragma unroll
        for (int o = 16; o; o >>= 1) x += __shfl_xor_sync(0xffffffffu, x, o);
        if (lane == 0) red[wid] = x;
        __syncthreads();
        if (tid == 0) {
            float s = 0.f;
            #pragma unroll
            for (int w = 0; w < 8; w++) s += red[w];
            *s_invp = 1.f / fmaxf(sqrtf(s), EPSN);
        }
        __syncthreads();
    }
    float s_inv = *s_invp;
    if (bid <= 1)      a = qv * s_inv;
    else if (bid == 2) a = 1.f/256.f;
    else               a = 0.f;
    a_s[tid] = a;

    const int j0 = wid * 4;
    float wreg[4][8];
    float creg[4] = {0.f, 0.f, 0.f, 0.f};

    {
        int chunk = fwd ? 0 : (nch - 1);
        const float* Wp = g_W + (size_t)(slot0 + chunk) * CH * DK;
        #pragma unroll
        for (int r = 0; r < 4; r++)
            #pragma unroll
            for (int m = 0; m < 8; m++)
                wreg[r][m] = Wp[(j0 + r)*DK + lane + 32*m];
        if (fwd) {
            #pragma unroll
            for (int r = 0; r < 4; r++) creg[r] = g_c[chunk*CH + j0 + r];
        }
    }

    float outreg = 0.f;

    for (int c = 0; c < nch; c++) {
        const int chunk = fwd ? c : (nch - 1 - c);
        const int lo  = chunk * CH;
        const int len = min(CH, steps - lo);
        const int hi  = lo + len - 1;
        __syncthreads();

        float kreg[CH], vreg[CH];
        #pragma unroll
        for (int j = 0; j < CH; j++) {
            int row = fwd ? (lo + j) : (hi - j);
            row = max(0, min(row, steps - 1));
            kreg[j] = Kd[row*DK + tid];
            vreg[j] = fwd ? 0.f : Vd[row*DK + tid];
        }

        float av[8];
        #pragma unroll
        for (int m = 0; m < 8; m++) av[m] = a_s[lane + 32*m];
        float s[4];
        #pragma unroll
        for (int r = 0; r < 4; r++) {
            float t = 0.f;
            #pragma unroll
            for (int m = 0; m < 8; m++) t += wreg[r][m] * av[m];
            s[r] = t;
        }
        #pragma unroll
        for (int o = 16; o; o >>= 1)
            #pragma unroll
            for (int r = 0; r < 4; r++)
                s[r] += __shfl_xor_sync(0xffffffffu, s[r], o);
        if (lane == 0) {
            #pragma unroll
            for (int r = 0; r < 4; r++) {
                int j = j0 + r;
                float sk = 0.f, sv = 0.f;
                if (j < len) {
                    if (fwd) { sk = -ALPHA * s[r] + creg[r]; }
                    else     { sk = -ALPHA * s[r]; sv = BETA * dpow[j] * s[r]; }
                }
                sigk_s[j] = sk;
                sigv_s[j] = sv;
            }
        }

        if (c + 1 < nch) {
            int nchunk = fwd ? (c + 1) : (nch - 2 - c);
            const float* Wp = g_W + (size_t)(slot0 + nchunk) * CH * DK;
            #pragma unroll
            for (int r = 0; r < 4; r++)
                #pragma unroll
                for (int m = 0; m < 8; m++)
                    wreg[r][m] = Wp[(j0 + r)*DK + lane + 32*m];
            if (fwd) {
                #pragma unroll
                for (int r = 0; r < 4; r++) creg[r] = g_c[nchunk*CH + j0 + r];
            }
        }
        __syncthreads();

        float wsum = 0.f, osum = 0.f;
        #pragma unroll
        for (int j = 0; j < CH; j++) {
            wsum += sigk_s[j] * kreg[j];
            osum += sigv_s[j] * vreg[j];
        }
        outreg += osum;
        a = dpow[len] * (a + wsum);
        a_s[tid] = a;
    }

    if (bid != 0) {
        // publish and arrive
        if (bid < 3) g_res[bid*DK + tid] = outreg;
        else         g_res[3*DK + tid]   = a;
        __threadfence();
        __syncthreads();
        if (tid == 0) atomicAdd(&g_done, 1);
        return;
    }

    // ---- block 0: wait for blocks 1..3, then final combine ----
    if (tid == 0) {
        while (*(volatile int*)&g_done < 3) { }
    }
    __threadfence();
    __syncthreads();

    float r1  = g_res[1*DK + tid];   // para recall (q probe)
    float r2  = g_res[2*DK + tid];   // doc_v
    float dkv = g_res[3*DK + tid];   // doc_k
    float ssd = bred256(dkv*dkv, red);
    float dot = bred256(qv*dkv, red);
    float coef = dot * s_inv / fmaxf(sqrtf(ssd), EPSN);
    out[tid] = 0.2f*outreg + 0.3f*r1 + 0.5f*(BETA*coef)*r2;

    __syncthreads();
    if (tid == 0) { g_bar1 = 0; g_bar2 = 0; g_done = 0; }   // reset for next replay
}

// ---------------- the single fused kernel ----------------
__global__ void __launch_bounds__(256, 1) k_mega(
                     const float* __restrict__ emb, const float* __restrict__ q,
                     const float* __restrict__ Wk, const float* __restrict__ bk,
                     const float* __restrict__ Wv, const float* __restrict__ bv,
                     float* __restrict__ out,
                     int T, int P, int nchS, int nchP, int nKV, int nPrep)
{
    extern __shared__ __align__(16) float dyn[];
    __shared__ __align__(8) unsigned long long mb[NBUF];

    const int bid = blockIdx.x, tid = threadIdx.x;

    // ---- phase 1: K/V projection (all blocks) ----
    kv_phase(dyn, mb, emb, Wk, bk, Wv, bv, T);

    // barrier 1: all nKV blocks
    __threadfence();
    __syncthreads();
    if (tid == 0) atomicAdd(&g_bar1, 1);
    if (bid >= nPrep) return;
    if (tid == 0) { while (*(volatile int*)&g_bar1 < nKV) { } }
    __threadfence();
    __syncthreads();

    // ---- phase 2: prep (blocks 0..nPrep-1) ----
    prep_phase(dyn, bid, T, P, nchS, nchP);

    // barrier 2: nPrep blocks
    __threadfence();
    __syncthreads();
    if (tid == 0) atomicAdd(&g_bar2, 1);
    if (bid >= 4) return;
    if (tid == 0) { while (*(volatile int*)&g_bar2 < nPrep) { } }
    __threadfence();
    __syncthreads();

    // ---- phase 3: scans + final (blocks 0..3) ----
    scan_phase(dyn, bid, q, out, T, P, nchS, nchP);
}

// ---------------- launcher ----------------
extern "C" void kernel_launch(void* const* d_in, const int* in_sizes, int n_in,
                              void* d_out, int out_size)
{
    const float* emb = (const float*)d_in[0];
    const float* q   = (const float*)d_in[1];
    const float* Wk  = (const float*)d_in[2];
    const float* bk  = (const float*)d_in[3];
    const float* Wv  = (const float*)d_in[4];
    const float* bv  = (const float*)d_in[5];
    // d_in[6..8] = zero initial memories (collapsed analytically)

    int T = in_sizes[0] / DEMB;     // 1000
    int P = T / 5;                  // 200
    int nchS = (T + CH - 1) / CH;   // 32
    int nchP = (P + CH - 1) / CH;   // 7
    int nKV  = (T + 7) / 8;         // 125 (<= 148 SMs: all co-resident)
    int nPrep = nchS + 2*nchP;      // 46

    cudaFuncSetAttribute(k_mega, cudaFuncAttributeMaxDynamicSharedMemorySize, DYN_BYTES);

    k_mega<<<nKV, 256, DYN_BYTES>>>(emb, q, Wk, bk, Wv, bv, (float*)d_out,
                                    T, P, nchS, nchP, nKV, nPrep);
}